// round 10
// baseline (speedup 1.0000x reference)
#include <cuda_runtime.h>
#include <cuda_bf16.h>
#include <cstdint>

// ---------------------------------------------------------------------------
// NetVLAD on GB300 — round 9: F(4x4,3x3) Winograd; GEMM retiled to 64x64
// warp tiles (CTA 128x256, 1 CTA/SM); assign_softmax 4-way c-split.
// ---------------------------------------------------------------------------

#define N_IMG   16
#define CHN     512
#define HWP     1024
#define KCL     64
#define NTILE   1024          // 16 img * 64 tiles (8x8 of 4x4 outputs)
#define NT      36            // 6x6 Winograd components
#define AP      40            // SMEM row pitch in bf16 (80B)
#define PPOS    1156          // 34*34 padded positions
#define PLANE_N (PPOS * CHN)

// GEMM stage layout (bytes): Ah 0, Al 10240, Bh 20480, Bl 40960
#define STAGE_BYTES 61440
#define OFF_AL 10240
#define OFF_BH 20480
#define OFF_BL 40960
#define GEMM_DSMEM (2 * STAGE_BYTES)
#define NCHUNK 16             // K=512 / 32

// -------- device scratch --------
__device__ __align__(16) __nv_bfloat16 g_U1h[NT * CHN * CHN];
__device__ __align__(16) __nv_bfloat16 g_U1l[NT * CHN * CHN];
__device__ __align__(16) __nv_bfloat16 g_U2h[NT * CHN * CHN];
__device__ __align__(16) __nv_bfloat16 g_U2l[NT * CHN * CHN];
__device__ __align__(16) __nv_bfloat16 g_Vh[NT * NTILE * CHN];
__device__ __align__(16) __nv_bfloat16 g_Vl[NT * NTILE * CHN];
__device__ __align__(16) float g_M[(size_t)NT * NTILE * CHN];
// conv1 output planes, halo-padded transposed: [n][(y+1)*34+(x+1)][c]
__device__ __align__(16) __nv_bfloat16 g_hh[N_IMG * PLANE_N];
__device__ __align__(16) __nv_bfloat16 g_hl[N_IMG * PLANE_N];
__device__ float g_invn[N_IMG * HWP];
__device__ float g_sa[N_IMG * KCL * HWP];
__device__ float g_ssum[N_IMG * KCL];
__device__ float g_vlad[N_IMG * KCL * CHN];
__device__ float g_rowss[N_IMG * KCL];
__device__ float g_bns[CHN];
__device__ float g_bnb[CHN];

// -------- helpers --------
__device__ __forceinline__ uint32_t smem_u32(const void* p) {
    uint32_t a;
    asm("{ .reg .u64 t; cvta.to.shared.u64 t, %1; cvt.u32.u64 %0, t; }"
        : "=r"(a) : "l"(p));
    return a;
}
__device__ __forceinline__ void ldm_x4(uint32_t r[4], uint32_t addr) {
    asm volatile("ldmatrix.sync.aligned.m8n8.x4.shared.b16 {%0,%1,%2,%3}, [%4];"
                 : "=r"(r[0]), "=r"(r[1]), "=r"(r[2]), "=r"(r[3]) : "r"(addr));
}
__device__ __forceinline__ void mma_bf16(float c[4], const uint32_t a[4],
                                         uint32_t b0, uint32_t b1) {
    asm volatile(
        "mma.sync.aligned.m16n8k16.row.col.f32.bf16.bf16.f32 "
        "{%0,%1,%2,%3}, {%4,%5,%6,%7}, {%8,%9}, {%0,%1,%2,%3};"
        : "+f"(c[0]), "+f"(c[1]), "+f"(c[2]), "+f"(c[3])
        : "r"(a[0]), "r"(a[1]), "r"(a[2]), "r"(a[3]), "r"(b0), "r"(b1));
}
__device__ __forceinline__ void cp_async16(uint32_t dst, const void* src) {
    asm volatile("cp.async.cg.shared.global [%0], [%1], 16;"
                 :: "r"(dst), "l"(src));
}
#define CP_COMMIT() asm volatile("cp.async.commit_group;" ::: "memory")
#define CP_WAIT(n)  asm volatile("cp.async.wait_group %0;" :: "n"(n) : "memory")

__device__ __forceinline__ void split_store(__nv_bfloat16* ph, __nv_bfloat16* pl,
                                            size_t off, float v) {
    __nv_bfloat16 h = __float2bfloat16(v);
    ph[off] = h;
    pl[off] = __float2bfloat16(v - __bfloat162float(h));
}

// ======================= prep: F(4,3) weight transform + BN fold ===========
__global__ void __launch_bounds__(256)
prep_wino_kernel(const float* __restrict__ w1, const float* __restrict__ w2,
                 const float* __restrict__ gamma, const float* __restrict__ beta,
                 const float* __restrict__ mean, const float* __restrict__ var) {
    int idx = blockIdx.x * 256 + threadIdx.x;
    const int per = CHN * CHN;
    if (idx < 2 * per) {
        int which = (idx >= per) ? 1 : 0;
        int r = idx - which * per;
        int oc = r >> 9;
        int ic = r & 511;
        const float* w = (which ? w2 : w1) + (size_t)oc * 4608 + ic * 9;
        float g[3][3];
#pragma unroll
        for (int i = 0; i < 3; i++)
#pragma unroll
            for (int j = 0; j < 3; j++) g[i][j] = w[i * 3 + j];
        float a[6][3];
#pragma unroll
        for (int c = 0; c < 3; c++) {
            float g0 = g[0][c], g1 = g[1][c], g2 = g[2][c];
            a[0][c] = 0.25f * g0;
            a[1][c] = (-1.f / 6.f) * (g0 + g1 + g2);
            a[2][c] = (-1.f / 6.f) * (g0 - g1 + g2);
            a[3][c] = (1.f / 24.f) * g0 + (1.f / 12.f) * g1 + (1.f / 6.f) * g2;
            a[4][c] = (1.f / 24.f) * g0 - (1.f / 12.f) * g1 + (1.f / 6.f) * g2;
            a[5][c] = g2;
        }
        __nv_bfloat16* Uh = which ? g_U2h : g_U1h;
        __nv_bfloat16* Ul = which ? g_U2l : g_U1l;
#pragma unroll
        for (int i = 0; i < 6; i++) {
            float b0 = a[i][0], b1 = a[i][1], b2 = a[i][2];
            float u[6];
            u[0] = 0.25f * b0;
            u[1] = (-1.f / 6.f) * (b0 + b1 + b2);
            u[2] = (-1.f / 6.f) * (b0 - b1 + b2);
            u[3] = (1.f / 24.f) * b0 + (1.f / 12.f) * b1 + (1.f / 6.f) * b2;
            u[4] = (1.f / 24.f) * b0 - (1.f / 12.f) * b1 + (1.f / 6.f) * b2;
            u[5] = b2;
#pragma unroll
            for (int j = 0; j < 6; j++) {
                int t = i * 6 + j;
                size_t off = ((size_t)t * CHN + oc) * CHN + ic;
                split_store(Uh, Ul, off, u[j]);
            }
        }
    }
    if (idx < CHN) {
        float inv = rsqrtf(var[idx] + 1e-5f);
        float s = gamma[idx] * inv;
        g_bns[idx] = s;
        g_bnb[idx] = beta[idx] - mean[idx] * s;
    }
}

// ======================= input transform: V = B^T d B =======================
__global__ void __launch_bounds__(256)
inx_kernel(const float* __restrict__ x, int which) {
    __shared__ float s_in[32 * 204];
    const int cb = blockIdx.x, ty = blockIdx.y, n = blockIdx.z;
    const int tid = threadIdx.x;

    if (which == 1) {
        const float* xN = x + ((size_t)n * CHN + cb * 32) * HWP;
        for (int i = tid; i < 6528; i += 256) {
            int c = i / 204;
            int rem = i - c * 204;
            int rr = rem / 34;
            int col = rem - rr * 34;
            int gy = 4 * ty - 1 + rr;
            int gx = col - 1;
            float v = 0.f;
            if ((unsigned)gy < 32u && (unsigned)gx < 32u)
                v = xN[(size_t)c * HWP + gy * 32 + gx];
            s_in[c * 204 + rr * 34 + col] = v;
        }
    } else {
        const __nv_bfloat16* hh = g_hh + (size_t)n * PLANE_N + cb * 32;
        const __nv_bfloat16* hl = g_hl + (size_t)n * PLANE_N + cb * 32;
        for (int i = tid; i < 6528; i += 256) {
            int c = i & 31;
            int j = i >> 5;
            int rr = j / 34;
            int col = j - rr * 34;
            size_t off = (size_t)((4 * ty + rr) * 34 + col) * CHN + c;
            float v = __bfloat162float(hh[off]) + __bfloat162float(hl[off]);
            s_in[c * 204 + rr * 34 + col] = v;
        }
    }
    __syncthreads();

    const int c = tid & 31, tx = tid >> 5;
    const float* dd = &s_in[c * 204];
    float d[6][6];
#pragma unroll
    for (int r = 0; r < 6; r++)
#pragma unroll
        for (int cc = 0; cc < 6; cc++)
            d[r][cc] = dd[r * 34 + 4 * tx + cc];
    float w[6][6];
#pragma unroll
    for (int cc = 0; cc < 6; cc++) {
        float d0 = d[0][cc], d1 = d[1][cc], d2 = d[2][cc];
        float d3 = d[3][cc], d4 = d[4][cc], d5 = d[5][cc];
        w[0][cc] = 4.f * d0 - 5.f * d2 + d4;
        w[1][cc] = -4.f * d1 - 4.f * d2 + d3 + d4;
        w[2][cc] = 4.f * d1 - 4.f * d2 - d3 + d4;
        w[3][cc] = -2.f * d1 - d2 + 2.f * d3 + d4;
        w[4][cc] = 2.f * d1 - d2 - 2.f * d3 + d4;
        w[5][cc] = 4.f * d1 - 5.f * d3 + d5;
    }
    int gtile = n * 64 + ty * 8 + tx;
    int ch = cb * 32 + c;
#pragma unroll
    for (int r = 0; r < 6; r++) {
        float d0 = w[r][0], d1 = w[r][1], d2 = w[r][2];
        float d3 = w[r][3], d4 = w[r][4], d5 = w[r][5];
        float v[6];
        v[0] = 4.f * d0 - 5.f * d2 + d4;
        v[1] = -4.f * d1 - 4.f * d2 + d3 + d4;
        v[2] = 4.f * d1 - 4.f * d2 - d3 + d4;
        v[3] = -2.f * d1 - d2 + 2.f * d3 + d4;
        v[4] = 2.f * d1 - d2 - 2.f * d3 + d4;
        v[5] = 4.f * d1 - 5.f * d3 + d5;
#pragma unroll
        for (int j = 0; j < 6; j++) {
            int t = r * 6 + j;
            size_t off = ((size_t)t * NTILE + gtile) * CHN + ch;
            split_store(g_Vh, g_Vl, off, v[j]);
        }
    }
}

// ======================= Winograd GEMM: CTA 128oc x 256nt, 64x64 warp tiles
__global__ void __launch_bounds__(256, 1)
gemm_wino_kernel(int which) {
    extern __shared__ __align__(16) char dynsm[];
    const uint32_t smbase = smem_u32(dynsm);

    const int tid = threadIdx.x;
    const int lane = tid & 31, warp = tid >> 5;
    const int wm = warp >> 2, wn = warp & 3;     // 2 x 4 warp grid
    const int nt0 = blockIdx.x * 256;
    const int oc0 = blockIdx.y * 128;
    const int t = blockIdx.z;

    const __nv_bfloat16* Uh = (which == 1) ? g_U1h : g_U2h;
    const __nv_bfloat16* Ul = (which == 1) ? g_U1l : g_U2l;

    const int frow = tid >> 1, fhalf = tid & 1;

    const int lt = lane >> 3, lr = lane & 7;
    const int a_row_off = (lt & 1) * 8 + lr;
    const int a_col_off = (lt >> 1) * 8;
    const int b_row_off = (lt >> 1) * 8 + lr;
    const int b_col_off = (lt & 1) * 8;

    float C[4][8][4];
#pragma unroll
    for (int mi = 0; mi < 4; mi++)
#pragma unroll
        for (int ni = 0; ni < 8; ni++)
#pragma unroll
            for (int q = 0; q < 4; q++) C[mi][ni][q] = 0.f;

    auto fill = [&](int chunk, int stage) {
        const int k0 = chunk << 5;
        const uint32_t sb = smbase + stage * STAGE_BYTES;
        {   // A: 128 rows, 2 threads/row
            size_t o = ((size_t)t * CHN + oc0 + frow) * CHN + k0 + fhalf * 16;
            uint32_t d = sb + frow * 80 + fhalf * 32;
            cp_async16(d, Uh + o);
            cp_async16(d + 16, Uh + o + 8);
            cp_async16(d + OFF_AL, Ul + o);
            cp_async16(d + OFF_AL + 16, Ul + o + 8);
        }
        {   // B: 256 rows, 1 thread/row, 64B each plane
            size_t o = ((size_t)t * NTILE + nt0 + tid) * CHN + k0;
            uint32_t dh = sb + OFF_BH + tid * 80;
            uint32_t dl = sb + OFF_BL + tid * 80;
            cp_async16(dh, g_Vh + o);
            cp_async16(dh + 16, g_Vh + o + 8);
            cp_async16(dh + 32, g_Vh + o + 16);
            cp_async16(dh + 48, g_Vh + o + 24);
            cp_async16(dl, g_Vl + o);
            cp_async16(dl + 16, g_Vl + o + 8);
            cp_async16(dl + 32, g_Vl + o + 16);
            cp_async16(dl + 48, g_Vl + o + 24);
        }
    };

    fill(0, 0); CP_COMMIT();
    fill(1, 1); CP_COMMIT();

    for (int chunk = 0; chunk < NCHUNK; ++chunk) {
        const int stage = chunk & 1;
        if (chunk == NCHUNK - 1) { CP_WAIT(0); } else { CP_WAIT(1); }
        __syncthreads();

        const uint32_t sb = smbase + stage * STAGE_BYTES;
#pragma unroll
        for (int s = 0; s < 2; ++s) {
            const int kk0 = s * 16;
            uint32_t Af[4][4], Bhf[4][4], Blf[4][4];
#pragma unroll
            for (int mi = 0; mi < 4; mi++) {
                int row = wm * 64 + mi * 16 + a_row_off;
                ldm_x4(Af[mi], sb + (uint32_t)(row * AP + kk0 + a_col_off) * 2);
            }
#pragma unroll
            for (int g = 0; g < 4; g++) {
                int row = wn * 64 + g * 16 + b_row_off;
                uint32_t off = (uint32_t)(row * AP + kk0 + b_col_off) * 2;
                ldm_x4(Bhf[g], sb + OFF_BH + off);
                ldm_x4(Blf[g], sb + OFF_BL + off);
            }
#pragma unroll
            for (int mi = 0; mi < 4; mi++)
#pragma unroll
                for (int ni = 0; ni < 8; ni++)
                    mma_bf16(C[mi][ni], Af[mi],
                             Bhf[ni >> 1][(ni & 1) * 2],
                             Bhf[ni >> 1][(ni & 1) * 2 + 1]);
#pragma unroll
            for (int mi = 0; mi < 4; mi++)
#pragma unroll
                for (int ni = 0; ni < 8; ni++)
                    mma_bf16(C[mi][ni], Af[mi],
                             Blf[ni >> 1][(ni & 1) * 2],
                             Blf[ni >> 1][(ni & 1) * 2 + 1]);
#pragma unroll
            for (int mi = 0; mi < 4; mi++) {
                int row = wm * 64 + mi * 16 + a_row_off;
                ldm_x4(Af[mi],
                       sb + OFF_AL + (uint32_t)(row * AP + kk0 + a_col_off) * 2);
            }
#pragma unroll
            for (int mi = 0; mi < 4; mi++)
#pragma unroll
                for (int ni = 0; ni < 8; ni++)
                    mma_bf16(C[mi][ni], Af[mi],
                             Bhf[ni >> 1][(ni & 1) * 2],
                             Bhf[ni >> 1][(ni & 1) * 2 + 1]);
        }

        if (chunk + 2 < NCHUNK) {
            __syncthreads();
            fill(chunk + 2, stage);
            CP_COMMIT();
        }
    }

    // epilogue: two 128-col halves, smem transpose -> g_M[t][tile][oc]
    __syncthreads();
    float* sC = reinterpret_cast<float*>(dynsm);       // pitch 132
    const int g = lane >> 2, t4 = lane & 3;
    for (int r = 0; r < 2; r++) {
        if ((wn >> 1) == r) {
            int wl = wn & 1;
#pragma unroll
            for (int mi = 0; mi < 4; mi++) {
                int ocA = wm * 64 + mi * 16 + g;
                int ocB = ocA + 8;
#pragma unroll
                for (int ni = 0; ni < 8; ni++) {
                    int nn = wl * 64 + ni * 8 + t4 * 2;
                    sC[nn * 132 + ocA] = C[mi][ni][0];
                    sC[(nn + 1) * 132 + ocA] = C[mi][ni][1];
                    sC[nn * 132 + ocB] = C[mi][ni][2];
                    sC[(nn + 1) * 132 + ocB] = C[mi][ni][3];
                }
            }
        }
        __syncthreads();
        float* Mo = g_M + ((size_t)t * NTILE + nt0 + r * 128) * CHN + oc0;
        for (int e = tid; e < 16384; e += 256) {
            int tl = e >> 7, ocl = e & 127;
            Mo[(size_t)tl * CHN + ocl] = sC[tl * 132 + ocl];
        }
        __syncthreads();
    }
}

// ======================= output transform helpers ==========================
__device__ __forceinline__ void at_rows(const float m[6], float o[4]) {
    o[0] = m[0] + m[1] + m[2] + m[3] + m[4];
    o[1] = m[1] - m[2] + 2.f * m[3] - 2.f * m[4];
    o[2] = m[1] + m[2] + 4.f * m[3] + 4.f * m[4];
    o[3] = m[1] - m[2] + 8.f * m[3] - 8.f * m[4] + m[5];
}

// ======================= output transform, conv1 ===========================
__global__ void __launch_bounds__(256)
outx1_kernel() {
    const int ocq = blockIdx.x, ty = blockIdx.y, n = blockIdx.z;
    const int tid = threadIdx.x;
    __nv_bfloat16* hh = g_hh + (size_t)n * PLANE_N;
    __nv_bfloat16* hl = g_hl + (size_t)n * PLANE_N;
#pragma unroll
    for (int it = 0; it < 4; it++) {
        int item = tid + it * 256;
        int oc = ocq * 128 + (item & 127);
        int tx = item >> 7;
        int gtile = n * 64 + ty * 8 + tx;
        float m[36];
#pragma unroll
        for (int t = 0; t < 36; t++)
            m[t] = g_M[((size_t)t * NTILE + gtile) * CHN + oc];
        float tmp[4][6];
#pragma unroll
        for (int j = 0; j < 6; j++) {
            float col[6];
#pragma unroll
            for (int i = 0; i < 6; i++) col[i] = m[i * 6 + j];
            float o[4];
            at_rows(col, o);
#pragma unroll
            for (int i = 0; i < 4; i++) tmp[i][j] = o[i];
        }
        float s = g_bns[oc], b = g_bnb[oc];
#pragma unroll
        for (int i = 0; i < 4; i++) {
            float o[4];
            at_rows(tmp[i], o);
#pragma unroll
            for (int j = 0; j < 4; j++) {
                float v = fmaxf(fmaf(o[j], s, b), 0.f);
                int pos = (4 * ty + i + 1) * 34 + (4 * tx + j + 1);
                split_store(hh, hl, (size_t)pos * CHN + oc, v);
            }
        }
    }
}

// ======================= output transform, conv2 -> x_enc fp32 =============
__global__ void __launch_bounds__(256)
outx2_kernel(float* __restrict__ out) {
    __shared__ float sO[64][132];
    const int ocq = blockIdx.x, ty = blockIdx.y, n = blockIdx.z;
    const int tid = threadIdx.x;
#pragma unroll
    for (int it = 0; it < 2; it++) {
        int item = tid + it * 256;
        int ocl = item & 63;
        int tx = item >> 6;
        int oc = ocq * 64 + ocl;
        int gtile = n * 64 + ty * 8 + tx;
        float m[36];
#pragma unroll
        for (int t = 0; t < 36; t++)
            m[t] = g_M[((size_t)t * NTILE + gtile) * CHN + oc];
        float tmp[4][6];
#pragma unroll
        for (int j = 0; j < 6; j++) {
            float col[6];
#pragma unroll
            for (int i = 0; i < 6; i++) col[i] = m[i * 6 + j];
            float o[4];
            at_rows(col, o);
#pragma unroll
            for (int i = 0; i < 4; i++) tmp[i][j] = o[i];
        }
#pragma unroll
        for (int i = 0; i < 4; i++) {
            float o[4];
            at_rows(tmp[i], o);
#pragma unroll
            for (int j = 0; j < 4; j++)
                sO[ocl][i * 33 + 4 * tx + j] = o[j];
        }
    }
    __syncthreads();
    float* oN = out + ((size_t)n * CHN + ocq * 64) * HWP;
    for (int e = tid; e < 8192; e += 256) {
        int ocl = e >> 7;
        int r2 = e & 127;
        int yy = r2 >> 5, col = r2 & 31;
        oN[(size_t)ocl * HWP + (4 * ty + yy) * 32 + col] = sO[ocl][yy * 33 + col];
    }
}

// ======================= assign + softmax (4-way c-split, 256 CTAs) ========
__global__ void __launch_bounds__(256)
assign_softmax_kernel(const float* __restrict__ xenc, const float* __restrict__ wa) {
    __shared__ float s_w[4][8][64];
    __shared__ float s_part[3][64][65];
    const int n = blockIdx.x >> 4;
    const int l0 = (blockIdx.x & 15) * 64;
    const int tid = threadIdx.x;
    const int grp = tid >> 6;          // 0..3, each covers 128 channels
    const int lt = tid & 63;
    const int l = l0 + lt;
    const int cbase = grp * 128;
    const float* xN = xenc + (size_t)n * CHN * HWP;

    float s[64];
#pragma unroll
    for (int k = 0; k < 64; k++) s[k] = 0.f;
    float ss = 0.f;

    for (int c0 = 0; c0 < 128; c0 += 8) {
#pragma unroll
        for (int r = 0; r < 8; r++) {
            int idx = lt + r * 64;
            int cc = idx >> 6, k = idx & 63;
            s_w[grp][cc][k] = wa[k * 512 + cbase + c0 + cc];
        }
        __syncthreads();
#pragma unroll
        for (int cc = 0; cc < 8; cc++) {
            float xv = xN[(cbase + c0 + cc) * HWP + l];
            ss = fmaf(xv, xv, ss);
#pragma unroll
            for (int k = 0; k < 64; k++) s[k] = fmaf(xv, s_w[grp][cc][k], s[k]);
        }
        __syncthreads();
    }

    if (grp > 0) {
#pragma unroll
        for (int k = 0; k < 64; k++) s_part[grp - 1][lt][k] = s[k];
        s_part[grp - 1][lt][64] = ss;
    }
    __syncthreads();
    if (grp == 0) {
#pragma unroll
        for (int k = 0; k < 64; k++)
            s[k] += s_part[0][lt][k] + s_part[1][lt][k] + s_part[2][lt][k];
        ss += s_part[0][lt][64] + s_part[1][lt][64] + s_part[2][lt][64];

        float invn = 1.f / fmaxf(sqrtf(ss), 1e-12f);
        g_invn[n * HWP + l] = invn;

        float mx = -1e30f;
#pragma unroll
        for (int k = 0; k < 64; k++) { s[k] *= invn; mx = fmaxf(mx, s[k]); }
        float sum = 0.f;
#pragma unroll
        for (int k = 0; k < 64; k++) { s[k] = expf(s[k] - mx); sum += s[k]; }
        float rs = 1.f / sum;
#pragma unroll
        for (int k = 0; k < 64; k++)
            g_sa[((size_t)n * 64 + k) * HWP + l] = s[k] * rs;
    }
}

// ======================= ssum =======================
__global__ void ssum_kernel() {
    int row = blockIdx.x;
    int tid = threadIdx.x;
    const float4* p = reinterpret_cast<const float4*>(g_sa + (size_t)row * HWP);
    float4 v = p[tid];
    float t = v.x + v.y + v.z + v.w;
    __shared__ float red[256];
    red[tid] = t;
    __syncthreads();
    for (int s = 128; s > 0; s >>= 1) {
        if (tid < s) red[tid] += red[tid + s];
        __syncthreads();
    }
    if (tid == 0) g_ssum[row] = red[0];
}

// ======================= VLAD =======================
__global__ void __launch_bounds__(256)
vlad_kernel(const float* __restrict__ xenc, const float* __restrict__ cent) {
    __shared__ float s_sa[8][1024];
    __shared__ float s_in[1024];
    const int n = blockIdx.x >> 3;
    const int k0 = (blockIdx.x & 7) * 8;
    const int tid = threadIdx.x;

    for (int i = tid; i < 1024; i += 256) s_in[i] = g_invn[n * HWP + i];
    for (int i = tid; i < 8192; i += 256) {
        int kk = i >> 10, l = i & 1023;
        s_sa[kk][l] = g_sa[((size_t)n * 64 + k0 + kk) * HWP + l];
    }
    __syncthreads();

    const int warp = tid >> 5, lane = tid & 31;
    const float* xN = xenc + (size_t)n * CHN * HWP;

    for (int c = warp; c < 512; c += 8) {
        float acc[8];
#pragma unroll
        for (int kk = 0; kk < 8; kk++) acc[kk] = 0.f;
        for (int l = lane; l < 1024; l += 32) {
            float xv = xN[c * HWP + l] * s_in[l];
#pragma unroll
            for (int kk = 0; kk < 8; kk++) acc[kk] = fmaf(xv, s_sa[kk][l], acc[kk]);
        }
#pragma unroll
        for (int kk = 0; kk < 8; kk++) {
            float v = acc[kk];
#pragma unroll
            for (int o = 16; o > 0; o >>= 1) v += __shfl_down_sync(0xffffffffu, v, o);
            if (lane == 0) {
                int k = k0 + kk;
                g_vlad[((size_t)n * 64 + k) * 512 + c] =
                    v - g_ssum[n * 64 + k] * cent[k * 512 + c];
            }
        }
    }
}

// ======================= intra norm =======================
__global__ void intra_kernel(float* __restrict__ out_vlad) {
    int row = blockIdx.x;
    int tid = threadIdx.x;
    const float2* p = reinterpret_cast<const float2*>(g_vlad + (size_t)row * 512);
    float2 v = p[tid];
    float ssq = v.x * v.x + v.y * v.y;
    __shared__ float red[256];
    red[tid] = ssq;
    __syncthreads();
    for (int s = 128; s > 0; s >>= 1) {
        if (tid < s) red[tid] += red[tid + s];
        __syncthreads();
    }
    float ss = red[0];
    float inv = 1.f / fmaxf(sqrtf(ss), 1e-12f);
    float2* o = reinterpret_cast<float2*>(out_vlad + (size_t)row * 512);
    float2 w;
    w.x = v.x * inv;
    w.y = v.y * inv;
    o[tid] = w;
    if (tid == 0) g_rowss[row] = ss * inv * inv;
}

// ======================= global scale =======================
__global__ void gscale_kernel(float* __restrict__ out_vlad) {
    int n = blockIdx.x;
    int tid = threadIdx.x;
    __shared__ float red[64];
    __shared__ float gsc;
    if (tid < 64) red[tid] = g_rowss[n * 64 + tid];
    __syncthreads();
    if (tid == 0) {
        float t = 0.f;
        for (int i = 0; i < 64; i++) t += red[i];
        gsc = 1.f / fmaxf(sqrtf(t), 1e-12f);
    }
    __syncthreads();
    float g = gsc;
    float* o = out_vlad + (size_t)n * (KCL * CHN);
    for (int i = tid; i < KCL * CHN; i += 256) o[i] *= g;
}

// ======================= launcher =======================
extern "C" void kernel_launch(void* const* d_in, const int* in_sizes, int n_in,
                              void* d_out, int out_size) {
    const float* x     = (const float*)d_in[0];
    const float* w1    = (const float*)d_in[1];
    const float* gamma = (const float*)d_in[2];
    const float* beta  = (const float*)d_in[3];
    const float* mean  = (const float*)d_in[4];
    const float* var   = (const float*)d_in[5];
    const float* w2    = (const float*)d_in[6];
    const float* wa    = (const float*)d_in[7];
    const float* cent  = (const float*)d_in[8];

    float* out = (float*)d_out;
    float* out_vlad = out;
    float* out_xenc = out + (size_t)N_IMG * KCL * CHN;

    static int smem_set = 0;
    if (!smem_set) {
        cudaFuncSetAttribute(gemm_wino_kernel,
                             cudaFuncAttributeMaxDynamicSharedMemorySize,
                             GEMM_DSMEM);
        smem_set = 1;
    }

    prep_wino_kernel<<<2048, 256>>>(w1, w2, gamma, beta, mean, var);

    dim3 tgrid(16, 8, N_IMG);
    dim3 ggrid(4, 4, NT);
    dim3 o1grid(4, 8, N_IMG);
    dim3 o2grid(8, 8, N_IMG);

    inx_kernel<<<tgrid, 256>>>(x, 1);
    gemm_wino_kernel<<<ggrid, 256, GEMM_DSMEM>>>(1);
    outx1_kernel<<<o1grid, 256>>>();

    inx_kernel<<<tgrid, 256>>>(nullptr, 2);
    gemm_wino_kernel<<<ggrid, 256, GEMM_DSMEM>>>(2);
    outx2_kernel<<<o2grid, 256>>>(out_xenc);

    assign_softmax_kernel<<<N_IMG * 16, 256>>>(out_xenc, wa);
    ssum_kernel<<<N_IMG * KCL, 256>>>();
    vlad_kernel<<<N_IMG * 8, 256>>>(out_xenc, cent);
    intra_kernel<<<N_IMG * KCL, 256>>>(out_vlad);
    gscale_kernel<<<N_IMG, 256>>>(out_vlad);
}

// round 11
// speedup vs baseline: 1.0811x; 1.0811x over previous
#include <cuda_runtime.h>
#include <cuda_bf16.h>
#include <cstdint>

// ---------------------------------------------------------------------------
// NetVLAD on GB300 — round 10: R8 Winograd F(4x4,3x3) GEMM config restored
// (128x128 CTA tiles, 2 CTA/SM); fp32 conv1 plane; 4-way-split assign.
// ---------------------------------------------------------------------------

#define N_IMG   16
#define CHN     512
#define HWP     1024
#define KCL     64
#define NTILE   1024          // 16 img * 64 tiles (8x8 of 4x4 outputs)
#define NT      36            // 6x6 Winograd components
#define AP      40            // SMEM row pitch in bf16 (80B)
#define PPOS    1156          // 34*34 padded positions
#define PLANE_N (PPOS * CHN)

// GEMM stage layout (bytes): Ah 0, Al 10240, Bh 20480, Bl 30720
#define STAGE_BYTES 40960
#define OFF_AL 10240
#define OFF_BH 20480
#define OFF_BL 30720
#define GEMM_DSMEM (2 * STAGE_BYTES)
#define NCHUNK 16             // K=512 / 32

// -------- device scratch --------
__device__ __align__(16) __nv_bfloat16 g_U1h[NT * CHN * CHN];
__device__ __align__(16) __nv_bfloat16 g_U1l[NT * CHN * CHN];
__device__ __align__(16) __nv_bfloat16 g_U2h[NT * CHN * CHN];
__device__ __align__(16) __nv_bfloat16 g_U2l[NT * CHN * CHN];
__device__ __align__(16) __nv_bfloat16 g_Vh[NT * NTILE * CHN];
__device__ __align__(16) __nv_bfloat16 g_Vl[NT * NTILE * CHN];
__device__ __align__(16) float g_M[(size_t)NT * NTILE * CHN];
// conv1 output plane, halo-padded transposed: [n][(y+1)*34+(x+1)][c], fp32
__device__ __align__(16) float g_hf[N_IMG * PLANE_N];
__device__ float g_invn[N_IMG * HWP];
__device__ float g_sa[N_IMG * KCL * HWP];
__device__ float g_ssum[N_IMG * KCL];
__device__ float g_vlad[N_IMG * KCL * CHN];
__device__ float g_rowss[N_IMG * KCL];
__device__ float g_bns[CHN];
__device__ float g_bnb[CHN];

// -------- helpers --------
__device__ __forceinline__ uint32_t smem_u32(const void* p) {
    uint32_t a;
    asm("{ .reg .u64 t; cvta.to.shared.u64 t, %1; cvt.u32.u64 %0, t; }"
        : "=r"(a) : "l"(p));
    return a;
}
__device__ __forceinline__ void ldm_x4(uint32_t r[4], uint32_t addr) {
    asm volatile("ldmatrix.sync.aligned.m8n8.x4.shared.b16 {%0,%1,%2,%3}, [%4];"
                 : "=r"(r[0]), "=r"(r[1]), "=r"(r[2]), "=r"(r[3]) : "r"(addr));
}
__device__ __forceinline__ void mma_bf16(float c[4], const uint32_t a[4],
                                         uint32_t b0, uint32_t b1) {
    asm volatile(
        "mma.sync.aligned.m16n8k16.row.col.f32.bf16.bf16.f32 "
        "{%0,%1,%2,%3}, {%4,%5,%6,%7}, {%8,%9}, {%0,%1,%2,%3};"
        : "+f"(c[0]), "+f"(c[1]), "+f"(c[2]), "+f"(c[3])
        : "r"(a[0]), "r"(a[1]), "r"(a[2]), "r"(a[3]), "r"(b0), "r"(b1));
}
__device__ __forceinline__ void cp_async16(uint32_t dst, const void* src) {
    asm volatile("cp.async.cg.shared.global [%0], [%1], 16;"
                 :: "r"(dst), "l"(src));
}
#define CP_COMMIT() asm volatile("cp.async.commit_group;" ::: "memory")
#define CP_WAIT(n)  asm volatile("cp.async.wait_group %0;" :: "n"(n) : "memory")

__device__ __forceinline__ void split_store(__nv_bfloat16* ph, __nv_bfloat16* pl,
                                            size_t off, float v) {
    __nv_bfloat16 h = __float2bfloat16(v);
    ph[off] = h;
    pl[off] = __float2bfloat16(v - __bfloat162float(h));
}

// ======================= prep: F(4,3) weight transform + BN fold ===========
__global__ void __launch_bounds__(256)
prep_wino_kernel(const float* __restrict__ w1, const float* __restrict__ w2,
                 const float* __restrict__ gamma, const float* __restrict__ beta,
                 const float* __restrict__ mean, const float* __restrict__ var) {
    int idx = blockIdx.x * 256 + threadIdx.x;
    const int per = CHN * CHN;
    if (idx < 2 * per) {
        int which = (idx >= per) ? 1 : 0;
        int r = idx - which * per;
        int oc = r >> 9;
        int ic = r & 511;
        const float* w = (which ? w2 : w1) + (size_t)oc * 4608 + ic * 9;
        float g[3][3];
#pragma unroll
        for (int i = 0; i < 3; i++)
#pragma unroll
            for (int j = 0; j < 3; j++) g[i][j] = w[i * 3 + j];
        float a[6][3];
#pragma unroll
        for (int c = 0; c < 3; c++) {
            float g0 = g[0][c], g1 = g[1][c], g2 = g[2][c];
            a[0][c] = 0.25f * g0;
            a[1][c] = (-1.f / 6.f) * (g0 + g1 + g2);
            a[2][c] = (-1.f / 6.f) * (g0 - g1 + g2);
            a[3][c] = (1.f / 24.f) * g0 + (1.f / 12.f) * g1 + (1.f / 6.f) * g2;
            a[4][c] = (1.f / 24.f) * g0 - (1.f / 12.f) * g1 + (1.f / 6.f) * g2;
            a[5][c] = g2;
        }
        __nv_bfloat16* Uh = which ? g_U2h : g_U1h;
        __nv_bfloat16* Ul = which ? g_U2l : g_U1l;
#pragma unroll
        for (int i = 0; i < 6; i++) {
            float b0 = a[i][0], b1 = a[i][1], b2 = a[i][2];
            float u[6];
            u[0] = 0.25f * b0;
            u[1] = (-1.f / 6.f) * (b0 + b1 + b2);
            u[2] = (-1.f / 6.f) * (b0 - b1 + b2);
            u[3] = (1.f / 24.f) * b0 + (1.f / 12.f) * b1 + (1.f / 6.f) * b2;
            u[4] = (1.f / 24.f) * b0 - (1.f / 12.f) * b1 + (1.f / 6.f) * b2;
            u[5] = b2;
#pragma unroll
            for (int j = 0; j < 6; j++) {
                int t = i * 6 + j;
                size_t off = ((size_t)t * CHN + oc) * CHN + ic;
                split_store(Uh, Ul, off, u[j]);
            }
        }
    }
    if (idx < CHN) {
        float inv = rsqrtf(var[idx] + 1e-5f);
        float s = gamma[idx] * inv;
        g_bns[idx] = s;
        g_bnb[idx] = beta[idx] - mean[idx] * s;
    }
}

// ======================= input transform: V = B^T d B =======================
__global__ void __launch_bounds__(256)
inx_kernel(const float* __restrict__ x, int which) {
    __shared__ float s_in[32 * 204];
    const int cb = blockIdx.x, ty = blockIdx.y, n = blockIdx.z;
    const int tid = threadIdx.x;

    if (which == 1) {
        const float* xN = x + ((size_t)n * CHN + cb * 32) * HWP;
        for (int i = tid; i < 6528; i += 256) {
            int c = i / 204;
            int rem = i - c * 204;
            int rr = rem / 34;
            int col = rem - rr * 34;
            int gy = 4 * ty - 1 + rr;
            int gx = col - 1;
            float v = 0.f;
            if ((unsigned)gy < 32u && (unsigned)gx < 32u)
                v = xN[(size_t)c * HWP + gy * 32 + gx];
            s_in[c * 204 + rr * 34 + col] = v;
        }
    } else {
        const float* hf = g_hf + (size_t)n * PLANE_N + cb * 32;
        for (int i = tid; i < 6528; i += 256) {
            int c = i & 31;
            int j = i >> 5;
            int rr = j / 34;
            int col = j - rr * 34;
            s_in[c * 204 + rr * 34 + col] =
                hf[(size_t)((4 * ty + rr) * 34 + col) * CHN + c];
        }
    }
    __syncthreads();

    const int c = tid & 31, tx = tid >> 5;
    const float* dd = &s_in[c * 204];
    float d[6][6];
#pragma unroll
    for (int r = 0; r < 6; r++)
#pragma unroll
        for (int cc = 0; cc < 6; cc++)
            d[r][cc] = dd[r * 34 + 4 * tx + cc];
    float w[6][6];
#pragma unroll
    for (int cc = 0; cc < 6; cc++) {
        float d0 = d[0][cc], d1 = d[1][cc], d2 = d[2][cc];
        float d3 = d[3][cc], d4 = d[4][cc], d5 = d[5][cc];
        w[0][cc] = 4.f * d0 - 5.f * d2 + d4;
        w[1][cc] = -4.f * d1 - 4.f * d2 + d3 + d4;
        w[2][cc] = 4.f * d1 - 4.f * d2 - d3 + d4;
        w[3][cc] = -2.f * d1 - d2 + 2.f * d3 + d4;
        w[4][cc] = 2.f * d1 - d2 - 2.f * d3 + d4;
        w[5][cc] = 4.f * d1 - 5.f * d3 + d5;
    }
    int gtile = n * 64 + ty * 8 + tx;
    int ch = cb * 32 + c;
#pragma unroll
    for (int r = 0; r < 6; r++) {
        float d0 = w[r][0], d1 = w[r][1], d2 = w[r][2];
        float d3 = w[r][3], d4 = w[r][4], d5 = w[r][5];
        float v[6];
        v[0] = 4.f * d0 - 5.f * d2 + d4;
        v[1] = -4.f * d1 - 4.f * d2 + d3 + d4;
        v[2] = 4.f * d1 - 4.f * d2 - d3 + d4;
        v[3] = -2.f * d1 - d2 + 2.f * d3 + d4;
        v[4] = 2.f * d1 - d2 - 2.f * d3 + d4;
        v[5] = 4.f * d1 - 5.f * d3 + d5;
#pragma unroll
        for (int j = 0; j < 6; j++) {
            int t = r * 6 + j;
            size_t off = ((size_t)t * NTILE + gtile) * CHN + ch;
            split_store(g_Vh, g_Vl, off, v[j]);
        }
    }
}

// ======================= Winograd GEMM (bf16x3 mma.sync, 128x128, 2 CTA/SM)
__global__ void __launch_bounds__(256, 2)
gemm_wino_kernel(int which) {
    extern __shared__ __align__(16) char dynsm[];
    const uint32_t smbase = smem_u32(dynsm);

    const int tid = threadIdx.x;
    const int lane = tid & 31, warp = tid >> 5;
    const int wm = warp >> 2, wn = warp & 3;
    const int nt0 = blockIdx.x * 128;
    const int oc0 = blockIdx.y * 128;
    const int t = blockIdx.z;

    const __nv_bfloat16* Uh = (which == 1) ? g_U1h : g_U2h;
    const __nv_bfloat16* Ul = (which == 1) ? g_U1l : g_U2l;

    const int frow = tid >> 1, fhalf = tid & 1;

    const int lt = lane >> 3, lr = lane & 7;
    const int a_row_off = (lt & 1) * 8 + lr;
    const int a_col_off = (lt >> 1) * 8;
    const int b_row_off = (lt >> 1) * 8 + lr;
    const int b_col_off = (lt & 1) * 8;

    float C[4][4][4];
#pragma unroll
    for (int mi = 0; mi < 4; mi++)
#pragma unroll
        for (int ni = 0; ni < 4; ni++)
#pragma unroll
            for (int q = 0; q < 4; q++) C[mi][ni][q] = 0.f;

    auto fill = [&](int chunk, int stage) {
        const int k0 = chunk << 5;
        const uint32_t sb = smbase + stage * STAGE_BYTES;
        {
            size_t o = ((size_t)t * CHN + oc0 + frow) * CHN + k0 + fhalf * 16;
            uint32_t d = sb + frow * 80 + fhalf * 32;
            cp_async16(d, Uh + o);
            cp_async16(d + 16, Uh + o + 8);
            cp_async16(d + OFF_AL, Ul + o);
            cp_async16(d + OFF_AL + 16, Ul + o + 8);
        }
        {
            size_t o = ((size_t)t * NTILE + nt0 + frow) * CHN + k0 + fhalf * 16;
            uint32_t d = sb + frow * 80 + fhalf * 32;
            cp_async16(d + OFF_BH, g_Vh + o);
            cp_async16(d + OFF_BH + 16, g_Vh + o + 8);
            cp_async16(d + OFF_BL, g_Vl + o);
            cp_async16(d + OFF_BL + 16, g_Vl + o + 8);
        }
    };

    fill(0, 0); CP_COMMIT();
    fill(1, 1); CP_COMMIT();

    for (int chunk = 0; chunk < NCHUNK; ++chunk) {
        const int stage = chunk & 1;
        if (chunk == NCHUNK - 1) { CP_WAIT(0); } else { CP_WAIT(1); }
        __syncthreads();

        const uint32_t sb = smbase + stage * STAGE_BYTES;
#pragma unroll
        for (int s = 0; s < 2; ++s) {
            const int kk0 = s * 16;
            uint32_t Af[4][4], Bhf[2][4], Blf[2][4];
#pragma unroll
            for (int mi = 0; mi < 4; mi++) {
                int row = wm * 64 + mi * 16 + a_row_off;
                ldm_x4(Af[mi], sb + (uint32_t)(row * AP + kk0 + a_col_off) * 2);
            }
#pragma unroll
            for (int g = 0; g < 2; g++) {
                int row = wn * 32 + g * 16 + b_row_off;
                uint32_t off = (uint32_t)(row * AP + kk0 + b_col_off) * 2;
                ldm_x4(Bhf[g], sb + OFF_BH + off);
                ldm_x4(Blf[g], sb + OFF_BL + off);
            }
#pragma unroll
            for (int mi = 0; mi < 4; mi++)
#pragma unroll
                for (int ni = 0; ni < 4; ni++)
                    mma_bf16(C[mi][ni], Af[mi],
                             Bhf[ni >> 1][(ni & 1) * 2],
                             Bhf[ni >> 1][(ni & 1) * 2 + 1]);
#pragma unroll
            for (int mi = 0; mi < 4; mi++)
#pragma unroll
                for (int ni = 0; ni < 4; ni++)
                    mma_bf16(C[mi][ni], Af[mi],
                             Blf[ni >> 1][(ni & 1) * 2],
                             Blf[ni >> 1][(ni & 1) * 2 + 1]);
#pragma unroll
            for (int mi = 0; mi < 4; mi++) {
                int row = wm * 64 + mi * 16 + a_row_off;
                ldm_x4(Af[mi],
                       sb + OFF_AL + (uint32_t)(row * AP + kk0 + a_col_off) * 2);
            }
#pragma unroll
            for (int mi = 0; mi < 4; mi++)
#pragma unroll
                for (int ni = 0; ni < 4; ni++)
                    mma_bf16(C[mi][ni], Af[mi],
                             Bhf[ni >> 1][(ni & 1) * 2],
                             Bhf[ni >> 1][(ni & 1) * 2 + 1]);
        }

        if (chunk + 2 < NCHUNK) {
            __syncthreads();
            fill(chunk + 2, stage);
            CP_COMMIT();
        }
    }

    // epilogue: transpose through smem -> g_M[t][tile][oc]
    __syncthreads();
    float* sC = reinterpret_cast<float*>(dynsm);       // pitch 132
    const int g = lane >> 2, t4 = lane & 3;
#pragma unroll
    for (int mi = 0; mi < 4; mi++) {
        int ocA = wm * 64 + mi * 16 + g;
        int ocB = ocA + 8;
#pragma unroll
        for (int ni = 0; ni < 4; ni++) {
            int nn = wn * 32 + ni * 8 + t4 * 2;
            sC[nn * 132 + ocA] = C[mi][ni][0];
            sC[(nn + 1) * 132 + ocA] = C[mi][ni][1];
            sC[nn * 132 + ocB] = C[mi][ni][2];
            sC[(nn + 1) * 132 + ocB] = C[mi][ni][3];
        }
    }
    __syncthreads();
    float* Mo = g_M + ((size_t)t * NTILE + nt0) * CHN + oc0;
    for (int e = tid; e < 16384; e += 256) {
        int tl = e >> 7, ocl = e & 127;
        Mo[(size_t)tl * CHN + ocl] = sC[tl * 132 + ocl];
    }
}

// ======================= output transform helpers ==========================
__device__ __forceinline__ void at_rows(const float m[6], float o[4]) {
    o[0] = m[0] + m[1] + m[2] + m[3] + m[4];
    o[1] = m[1] - m[2] + 2.f * m[3] - 2.f * m[4];
    o[2] = m[1] + m[2] + 4.f * m[3] + 4.f * m[4];
    o[3] = m[1] - m[2] + 8.f * m[3] - 8.f * m[4] + m[5];
}

// ======================= output transform, conv1 (fp32 plane) ==============
__global__ void __launch_bounds__(256)
outx1_kernel() {
    const int ocq = blockIdx.x, ty = blockIdx.y, n = blockIdx.z;
    const int tid = threadIdx.x;
    float* hf = g_hf + (size_t)n * PLANE_N;
#pragma unroll
    for (int it = 0; it < 4; it++) {
        int item = tid + it * 256;
        int oc = ocq * 128 + (item & 127);
        int tx = item >> 7;
        int gtile = n * 64 + ty * 8 + tx;
        float m[36];
#pragma unroll
        for (int t = 0; t < 36; t++)
            m[t] = g_M[((size_t)t * NTILE + gtile) * CHN + oc];
        float tmp[4][6];
#pragma unroll
        for (int j = 0; j < 6; j++) {
            float col[6];
#pragma unroll
            for (int i = 0; i < 6; i++) col[i] = m[i * 6 + j];
            float o[4];
            at_rows(col, o);
#pragma unroll
            for (int i = 0; i < 4; i++) tmp[i][j] = o[i];
        }
        float s = g_bns[oc], b = g_bnb[oc];
#pragma unroll
        for (int i = 0; i < 4; i++) {
            float o[4];
            at_rows(tmp[i], o);
#pragma unroll
            for (int j = 0; j < 4; j++) {
                float v = fmaxf(fmaf(o[j], s, b), 0.f);
                int pos = (4 * ty + i + 1) * 34 + (4 * tx + j + 1);
                hf[(size_t)pos * CHN + oc] = v;
            }
        }
    }
}

// ======================= output transform, conv2 -> x_enc fp32 =============
__global__ void __launch_bounds__(256)
outx2_kernel(float* __restrict__ out) {
    __shared__ float sO[64][132];
    const int ocq = blockIdx.x, ty = blockIdx.y, n = blockIdx.z;
    const int tid = threadIdx.x;
#pragma unroll
    for (int it = 0; it < 2; it++) {
        int item = tid + it * 256;
        int ocl = item & 63;
        int tx = item >> 6;
        int oc = ocq * 64 + ocl;
        int gtile = n * 64 + ty * 8 + tx;
        float m[36];
#pragma unroll
        for (int t = 0; t < 36; t++)
            m[t] = g_M[((size_t)t * NTILE + gtile) * CHN + oc];
        float tmp[4][6];
#pragma unroll
        for (int j = 0; j < 6; j++) {
            float col[6];
#pragma unroll
            for (int i = 0; i < 6; i++) col[i] = m[i * 6 + j];
            float o[4];
            at_rows(col, o);
#pragma unroll
            for (int i = 0; i < 4; i++) tmp[i][j] = o[i];
        }
#pragma unroll
        for (int i = 0; i < 4; i++) {
            float o[4];
            at_rows(tmp[i], o);
#pragma unroll
            for (int j = 0; j < 4; j++)
                sO[ocl][i * 33 + 4 * tx + j] = o[j];
        }
    }
    __syncthreads();
    float* oN = out + ((size_t)n * CHN + ocq * 64) * HWP;
    for (int e = tid; e < 8192; e += 256) {
        int ocl = e >> 7;
        int r2 = e & 127;
        int yy = r2 >> 5, col = r2 & 31;
        oN[(size_t)ocl * HWP + (4 * ty + yy) * 32 + col] = sO[ocl][yy * 33 + col];
    }
}

// ======================= assign + softmax (4-way c-split, 256 CTAs) ========
__global__ void __launch_bounds__(256)
assign_softmax_kernel(const float* __restrict__ xenc, const float* __restrict__ wa) {
    __shared__ float s_w[4][8][64];
    __shared__ float s_part[3][64][65];
    const int n = blockIdx.x >> 4;
    const int l0 = (blockIdx.x & 15) * 64;
    const int tid = threadIdx.x;
    const int grp = tid >> 6;          // 0..3, each covers 128 channels
    const int lt = tid & 63;
    const int l = l0 + lt;
    const int cbase = grp * 128;
    const float* xN = xenc + (size_t)n * CHN * HWP;

    float s[64];
#pragma unroll
    for (int k = 0; k < 64; k++) s[k] = 0.f;
    float ss = 0.f;

    for (int c0 = 0; c0 < 128; c0 += 8) {
#pragma unroll
        for (int r = 0; r < 8; r++) {
            int idx = lt + r * 64;
            int cc = idx >> 6, k = idx & 63;
            s_w[grp][cc][k] = wa[k * 512 + cbase + c0 + cc];
        }
        __syncthreads();
#pragma unroll
        for (int cc = 0; cc < 8; cc++) {
            float xv = xN[(cbase + c0 + cc) * HWP + l];
            ss = fmaf(xv, xv, ss);
#pragma unroll
            for (int k = 0; k < 64; k++) s[k] = fmaf(xv, s_w[grp][cc][k], s[k]);
        }
        __syncthreads();
    }

    if (grp > 0) {
#pragma unroll
        for (int k = 0; k < 64; k++) s_part[grp - 1][lt][k] = s[k];
        s_part[grp - 1][lt][64] = ss;
    }
    __syncthreads();
    if (grp == 0) {
#pragma unroll
        for (int k = 0; k < 64; k++)
            s[k] += s_part[0][lt][k] + s_part[1][lt][k] + s_part[2][lt][k];
        ss += s_part[0][lt][64] + s_part[1][lt][64] + s_part[2][lt][64];

        float invn = 1.f / fmaxf(sqrtf(ss), 1e-12f);
        g_invn[n * HWP + l] = invn;

        float mx = -1e30f;
#pragma unroll
        for (int k = 0; k < 64; k++) { s[k] *= invn; mx = fmaxf(mx, s[k]); }
        float sum = 0.f;
#pragma unroll
        for (int k = 0; k < 64; k++) { s[k] = expf(s[k] - mx); sum += s[k]; }
        float rs = 1.f / sum;
#pragma unroll
        for (int k = 0; k < 64; k++)
            g_sa[((size_t)n * 64 + k) * HWP + l] = s[k] * rs;
    }
}

// ======================= ssum =======================
__global__ void ssum_kernel() {
    int row = blockIdx.x;
    int tid = threadIdx.x;
    const float4* p = reinterpret_cast<const float4*>(g_sa + (size_t)row * HWP);
    float4 v = p[tid];
    float t = v.x + v.y + v.z + v.w;
    __shared__ float red[256];
    red[tid] = t;
    __syncthreads();
    for (int s = 128; s > 0; s >>= 1) {
        if (tid < s) red[tid] += red[tid + s];
        __syncthreads();
    }
    if (tid == 0) g_ssum[row] = red[0];
}

// ======================= VLAD =======================
__global__ void __launch_bounds__(256)
vlad_kernel(const float* __restrict__ xenc, const float* __restrict__ cent) {
    __shared__ float s_sa[8][1024];
    __shared__ float s_in[1024];
    const int n = blockIdx.x >> 3;
    const int k0 = (blockIdx.x & 7) * 8;
    const int tid = threadIdx.x;

    for (int i = tid; i < 1024; i += 256) s_in[i] = g_invn[n * HWP + i];
    for (int i = tid; i < 8192; i += 256) {
        int kk = i >> 10, l = i & 1023;
        s_sa[kk][l] = g_sa[((size_t)n * 64 + k0 + kk) * HWP + l];
    }
    __syncthreads();

    const int warp = tid >> 5, lane = tid & 31;
    const float* xN = xenc + (size_t)n * CHN * HWP;

    for (int c = warp; c < 512; c += 8) {
        float acc[8];
#pragma unroll
        for (int kk = 0; kk < 8; kk++) acc[kk] = 0.f;
        for (int l = lane; l < 1024; l += 32) {
            float xv = xN[c * HWP + l] * s_in[l];
#pragma unroll
            for (int kk = 0; kk < 8; kk++) acc[kk] = fmaf(xv, s_sa[kk][l], acc[kk]);
        }
#pragma unroll
        for (int kk = 0; kk < 8; kk++) {
            float v = acc[kk];
#pragma unroll
            for (int o = 16; o > 0; o >>= 1) v += __shfl_down_sync(0xffffffffu, v, o);
            if (lane == 0) {
                int k = k0 + kk;
                g_vlad[((size_t)n * 64 + k) * 512 + c] =
                    v - g_ssum[n * 64 + k] * cent[k * 512 + c];
            }
        }
    }
}

// ======================= intra norm =======================
__global__ void intra_kernel(float* __restrict__ out_vlad) {
    int row = blockIdx.x;
    int tid = threadIdx.x;
    const float2* p = reinterpret_cast<const float2*>(g_vlad + (size_t)row * 512);
    float2 v = p[tid];
    float ssq = v.x * v.x + v.y * v.y;
    __shared__ float red[256];
    red[tid] = ssq;
    __syncthreads();
    for (int s = 128; s > 0; s >>= 1) {
        if (tid < s) red[tid] += red[tid + s];
        __syncthreads();
    }
    float ss = red[0];
    float inv = 1.f / fmaxf(sqrtf(ss), 1e-12f);
    float2* o = reinterpret_cast<float2*>(out_vlad + (size_t)row * 512);
    float2 w;
    w.x = v.x * inv;
    w.y = v.y * inv;
    o[tid] = w;
    if (tid == 0) g_rowss[row] = ss * inv * inv;
}

// ======================= global scale =======================
__global__ void gscale_kernel(float* __restrict__ out_vlad) {
    int n = blockIdx.x;
    int tid = threadIdx.x;
    __shared__ float red[64];
    __shared__ float gsc;
    if (tid < 64) red[tid] = g_rowss[n * 64 + tid];
    __syncthreads();
    if (tid == 0) {
        float t = 0.f;
        for (int i = 0; i < 64; i++) t += red[i];
        gsc = 1.f / fmaxf(sqrtf(t), 1e-12f);
    }
    __syncthreads();
    float g = gsc;
    float* o = out_vlad + (size_t)n * (KCL * CHN);
    for (int i = tid; i < KCL * CHN; i += 256) o[i] *= g;
}

// ======================= launcher =======================
extern "C" void kernel_launch(void* const* d_in, const int* in_sizes, int n_in,
                              void* d_out, int out_size) {
    const float* x     = (const float*)d_in[0];
    const float* w1    = (const float*)d_in[1];
    const float* gamma = (const float*)d_in[2];
    const float* beta  = (const float*)d_in[3];
    const float* mean  = (const float*)d_in[4];
    const float* var   = (const float*)d_in[5];
    const float* w2    = (const float*)d_in[6];
    const float* wa    = (const float*)d_in[7];
    const float* cent  = (const float*)d_in[8];

    float* out = (float*)d_out;
    float* out_vlad = out;
    float* out_xenc = out + (size_t)N_IMG * KCL * CHN;

    static int smem_set = 0;
    if (!smem_set) {
        cudaFuncSetAttribute(gemm_wino_kernel,
                             cudaFuncAttributeMaxDynamicSharedMemorySize,
                             GEMM_DSMEM);
        smem_set = 1;
    }

    prep_wino_kernel<<<2048, 256>>>(w1, w2, gamma, beta, mean, var);

    dim3 tgrid(16, 8, N_IMG);
    dim3 ggrid(8, 4, NT);
    dim3 o1grid(4, 8, N_IMG);
    dim3 o2grid(8, 8, N_IMG);

    inx_kernel<<<tgrid, 256>>>(x, 1);
    gemm_wino_kernel<<<ggrid, 256, GEMM_DSMEM>>>(1);
    outx1_kernel<<<o1grid, 256>>>();

    inx_kernel<<<tgrid, 256>>>(nullptr, 2);
    gemm_wino_kernel<<<ggrid, 256, GEMM_DSMEM>>>(2);
    outx2_kernel<<<o2grid, 256>>>(out_xenc);

    assign_softmax_kernel<<<N_IMG * 16, 256>>>(out_xenc, wa);
    ssum_kernel<<<N_IMG * KCL, 256>>>();
    vlad_kernel<<<N_IMG * 8, 256>>>(out_xenc, cent);
    intra_kernel<<<N_IMG * KCL, 256>>>(out_vlad);
    gscale_kernel<<<N_IMG, 256>>>(out_vlad);
}

// round 12
// speedup vs baseline: 1.2923x; 1.1954x over previous
#include <cuda_runtime.h>
#include <cuda_bf16.h>
#include <cstdint>

// ---------------------------------------------------------------------------
// NetVLAD on GB300 — round 11: R8 Winograd F(4x4,3x3) base + f32x2-packed
// assign/vlad; vlad restructured to read x_enc once (smem-tiled GEMM).
// ---------------------------------------------------------------------------

#define N_IMG   16
#define CHN     512
#define HWP     1024
#define KCL     64
#define NTILE   1024          // 16 img * 64 tiles (8x8 of 4x4 outputs)
#define NT      36            // 6x6 Winograd components
#define AP      40            // SMEM row pitch in bf16 (80B)
#define PPOS    1156          // 34*34 padded positions
#define PLANE_N (PPOS * CHN)

// GEMM stage layout (bytes): Ah 0, Al 10240, Bh 20480, Bl 30720
#define STAGE_BYTES 40960
#define OFF_AL 10240
#define OFF_BH 20480
#define OFF_BL 30720
#define GEMM_DSMEM (2 * STAGE_BYTES)
#define NCHUNK 16             // K=512 / 32

#define VLAD_DSMEM 196608     // 8192 + 16384 ulonglong

typedef unsigned long long ull;

// -------- device scratch --------
__device__ __align__(16) __nv_bfloat16 g_U1h[NT * CHN * CHN];
__device__ __align__(16) __nv_bfloat16 g_U1l[NT * CHN * CHN];
__device__ __align__(16) __nv_bfloat16 g_U2h[NT * CHN * CHN];
__device__ __align__(16) __nv_bfloat16 g_U2l[NT * CHN * CHN];
__device__ __align__(16) __nv_bfloat16 g_Vh[NT * NTILE * CHN];
__device__ __align__(16) __nv_bfloat16 g_Vl[NT * NTILE * CHN];
__device__ __align__(16) float g_M[(size_t)NT * NTILE * CHN];
// conv1 output planes, halo-padded transposed: [n][(y+1)*34+(x+1)][c]
__device__ __align__(16) __nv_bfloat16 g_hh[N_IMG * PLANE_N];
__device__ __align__(16) __nv_bfloat16 g_hl[N_IMG * PLANE_N];
__device__ float g_invn[N_IMG * HWP];
__device__ float g_sa[N_IMG * KCL * HWP];
__device__ float g_ssum[N_IMG * KCL];
__device__ float g_vlad[N_IMG * KCL * CHN];
__device__ float g_rowss[N_IMG * KCL];
__device__ float g_bns[CHN];
__device__ float g_bnb[CHN];

// -------- helpers --------
__device__ __forceinline__ uint32_t smem_u32(const void* p) {
    uint32_t a;
    asm("{ .reg .u64 t; cvta.to.shared.u64 t, %1; cvt.u32.u64 %0, t; }"
        : "=r"(a) : "l"(p));
    return a;
}
__device__ __forceinline__ void ldm_x4(uint32_t r[4], uint32_t addr) {
    asm volatile("ldmatrix.sync.aligned.m8n8.x4.shared.b16 {%0,%1,%2,%3}, [%4];"
                 : "=r"(r[0]), "=r"(r[1]), "=r"(r[2]), "=r"(r[3]) : "r"(addr));
}
__device__ __forceinline__ void mma_bf16(float c[4], const uint32_t a[4],
                                         uint32_t b0, uint32_t b1) {
    asm volatile(
        "mma.sync.aligned.m16n8k16.row.col.f32.bf16.bf16.f32 "
        "{%0,%1,%2,%3}, {%4,%5,%6,%7}, {%8,%9}, {%0,%1,%2,%3};"
        : "+f"(c[0]), "+f"(c[1]), "+f"(c[2]), "+f"(c[3])
        : "r"(a[0]), "r"(a[1]), "r"(a[2]), "r"(a[3]), "r"(b0), "r"(b1));
}
__device__ __forceinline__ void cp_async16(uint32_t dst, const void* src) {
    asm volatile("cp.async.cg.shared.global [%0], [%1], 16;"
                 :: "r"(dst), "l"(src));
}
#define CP_COMMIT() asm volatile("cp.async.commit_group;" ::: "memory")
#define CP_WAIT(n)  asm volatile("cp.async.wait_group %0;" :: "n"(n) : "memory")

__device__ __forceinline__ void split_store(__nv_bfloat16* ph, __nv_bfloat16* pl,
                                            size_t off, float v) {
    __nv_bfloat16 h = __float2bfloat16(v);
    ph[off] = h;
    pl[off] = __float2bfloat16(v - __bfloat162float(h));
}

// packed f32x2
__device__ __forceinline__ ull fma2(ull a, ull b, ull c) {
    ull d;
    asm("fma.rn.f32x2 %0, %1, %2, %3;" : "=l"(d) : "l"(a), "l"(b), "l"(c));
    return d;
}
__device__ __forceinline__ ull pack2(float x, float y) {
    ull r;
    asm("mov.b64 %0, {%1, %2};" : "=l"(r) : "f"(x), "f"(y));
    return r;
}
__device__ __forceinline__ float2 unpack2(ull v) {
    float2 r;
    asm("mov.b64 {%0, %1}, %2;" : "=f"(r.x), "=f"(r.y) : "l"(v));
    return r;
}

// ======================= prep: F(4,3) weight transform + BN fold ===========
__global__ void __launch_bounds__(256)
prep_wino_kernel(const float* __restrict__ w1, const float* __restrict__ w2,
                 const float* __restrict__ gamma, const float* __restrict__ beta,
                 const float* __restrict__ mean, const float* __restrict__ var) {
    int idx = blockIdx.x * 256 + threadIdx.x;
    const int per = CHN * CHN;
    if (idx < 2 * per) {
        int which = (idx >= per) ? 1 : 0;
        int r = idx - which * per;
        int oc = r >> 9;
        int ic = r & 511;
        const float* w = (which ? w2 : w1) + (size_t)oc * 4608 + ic * 9;
        float g[3][3];
#pragma unroll
        for (int i = 0; i < 3; i++)
#pragma unroll
            for (int j = 0; j < 3; j++) g[i][j] = w[i * 3 + j];
        float a[6][3];
#pragma unroll
        for (int c = 0; c < 3; c++) {
            float g0 = g[0][c], g1 = g[1][c], g2 = g[2][c];
            a[0][c] = 0.25f * g0;
            a[1][c] = (-1.f / 6.f) * (g0 + g1 + g2);
            a[2][c] = (-1.f / 6.f) * (g0 - g1 + g2);
            a[3][c] = (1.f / 24.f) * g0 + (1.f / 12.f) * g1 + (1.f / 6.f) * g2;
            a[4][c] = (1.f / 24.f) * g0 - (1.f / 12.f) * g1 + (1.f / 6.f) * g2;
            a[5][c] = g2;
        }
        __nv_bfloat16* Uh = which ? g_U2h : g_U1h;
        __nv_bfloat16* Ul = which ? g_U2l : g_U1l;
#pragma unroll
        for (int i = 0; i < 6; i++) {
            float b0 = a[i][0], b1 = a[i][1], b2 = a[i][2];
            float u[6];
            u[0] = 0.25f * b0;
            u[1] = (-1.f / 6.f) * (b0 + b1 + b2);
            u[2] = (-1.f / 6.f) * (b0 - b1 + b2);
            u[3] = (1.f / 24.f) * b0 + (1.f / 12.f) * b1 + (1.f / 6.f) * b2;
            u[4] = (1.f / 24.f) * b0 - (1.f / 12.f) * b1 + (1.f / 6.f) * b2;
            u[5] = b2;
#pragma unroll
            for (int j = 0; j < 6; j++) {
                int t = i * 6 + j;
                size_t off = ((size_t)t * CHN + oc) * CHN + ic;
                split_store(Uh, Ul, off, u[j]);
            }
        }
    }
    if (idx < CHN) {
        float inv = rsqrtf(var[idx] + 1e-5f);
        float s = gamma[idx] * inv;
        g_bns[idx] = s;
        g_bnb[idx] = beta[idx] - mean[idx] * s;
    }
}

// ======================= input transform: V = B^T d B =======================
__global__ void __launch_bounds__(256)
inx_kernel(const float* __restrict__ x, int which) {
    __shared__ float s_in[32 * 204];
    const int cb = blockIdx.x, ty = blockIdx.y, n = blockIdx.z;
    const int tid = threadIdx.x;

    if (which == 1) {
        const float* xN = x + ((size_t)n * CHN + cb * 32) * HWP;
        for (int i = tid; i < 6528; i += 256) {
            int c = i / 204;
            int rem = i - c * 204;
            int rr = rem / 34;
            int col = rem - rr * 34;
            int gy = 4 * ty - 1 + rr;
            int gx = col - 1;
            float v = 0.f;
            if ((unsigned)gy < 32u && (unsigned)gx < 32u)
                v = xN[(size_t)c * HWP + gy * 32 + gx];
            s_in[c * 204 + rr * 34 + col] = v;
        }
    } else {
        const __nv_bfloat16* hh = g_hh + (size_t)n * PLANE_N + cb * 32;
        const __nv_bfloat16* hl = g_hl + (size_t)n * PLANE_N + cb * 32;
        for (int i = tid; i < 6528; i += 256) {
            int c = i & 31;
            int j = i >> 5;
            int rr = j / 34;
            int col = j - rr * 34;
            size_t off = (size_t)((4 * ty + rr) * 34 + col) * CHN + c;
            float v = __bfloat162float(hh[off]) + __bfloat162float(hl[off]);
            s_in[c * 204 + rr * 34 + col] = v;
        }
    }
    __syncthreads();

    const int c = tid & 31, tx = tid >> 5;
    const float* dd = &s_in[c * 204];
    float d[6][6];
#pragma unroll
    for (int r = 0; r < 6; r++)
#pragma unroll
        for (int cc = 0; cc < 6; cc++)
            d[r][cc] = dd[r * 34 + 4 * tx + cc];
    float w[6][6];
#pragma unroll
    for (int cc = 0; cc < 6; cc++) {
        float d0 = d[0][cc], d1 = d[1][cc], d2 = d[2][cc];
        float d3 = d[3][cc], d4 = d[4][cc], d5 = d[5][cc];
        w[0][cc] = 4.f * d0 - 5.f * d2 + d4;
        w[1][cc] = -4.f * d1 - 4.f * d2 + d3 + d4;
        w[2][cc] = 4.f * d1 - 4.f * d2 - d3 + d4;
        w[3][cc] = -2.f * d1 - d2 + 2.f * d3 + d4;
        w[4][cc] = 2.f * d1 - d2 - 2.f * d3 + d4;
        w[5][cc] = 4.f * d1 - 5.f * d3 + d5;
    }
    int gtile = n * 64 + ty * 8 + tx;
    int ch = cb * 32 + c;
#pragma unroll
    for (int r = 0; r < 6; r++) {
        float d0 = w[r][0], d1 = w[r][1], d2 = w[r][2];
        float d3 = w[r][3], d4 = w[r][4], d5 = w[r][5];
        float v[6];
        v[0] = 4.f * d0 - 5.f * d2 + d4;
        v[1] = -4.f * d1 - 4.f * d2 + d3 + d4;
        v[2] = 4.f * d1 - 4.f * d2 - d3 + d4;
        v[3] = -2.f * d1 - d2 + 2.f * d3 + d4;
        v[4] = 2.f * d1 - d2 - 2.f * d3 + d4;
        v[5] = 4.f * d1 - 5.f * d3 + d5;
#pragma unroll
        for (int j = 0; j < 6; j++) {
            int t = r * 6 + j;
            size_t off = ((size_t)t * NTILE + gtile) * CHN + ch;
            split_store(g_Vh, g_Vl, off, v[j]);
        }
    }
}

// ======================= Winograd GEMM (bf16x3 mma.sync, 128x128, 2 CTA/SM)
__global__ void __launch_bounds__(256, 2)
gemm_wino_kernel(int which) {
    extern __shared__ __align__(16) char dynsm[];
    const uint32_t smbase = smem_u32(dynsm);

    const int tid = threadIdx.x;
    const int lane = tid & 31, warp = tid >> 5;
    const int wm = warp >> 2, wn = warp & 3;
    const int nt0 = blockIdx.x * 128;
    const int oc0 = blockIdx.y * 128;
    const int t = blockIdx.z;

    const __nv_bfloat16* Uh = (which == 1) ? g_U1h : g_U2h;
    const __nv_bfloat16* Ul = (which == 1) ? g_U1l : g_U2l;

    const int frow = tid >> 1, fhalf = tid & 1;

    const int lt = lane >> 3, lr = lane & 7;
    const int a_row_off = (lt & 1) * 8 + lr;
    const int a_col_off = (lt >> 1) * 8;
    const int b_row_off = (lt >> 1) * 8 + lr;
    const int b_col_off = (lt & 1) * 8;

    float C[4][4][4];
#pragma unroll
    for (int mi = 0; mi < 4; mi++)
#pragma unroll
        for (int ni = 0; ni < 4; ni++)
#pragma unroll
            for (int q = 0; q < 4; q++) C[mi][ni][q] = 0.f;

    auto fill = [&](int chunk, int stage) {
        const int k0 = chunk << 5;
        const uint32_t sb = smbase + stage * STAGE_BYTES;
        {
            size_t o = ((size_t)t * CHN + oc0 + frow) * CHN + k0 + fhalf * 16;
            uint32_t d = sb + frow * 80 + fhalf * 32;
            cp_async16(d, Uh + o);
            cp_async16(d + 16, Uh + o + 8);
            cp_async16(d + OFF_AL, Ul + o);
            cp_async16(d + OFF_AL + 16, Ul + o + 8);
        }
        {
            size_t o = ((size_t)t * NTILE + nt0 + frow) * CHN + k0 + fhalf * 16;
            uint32_t d = sb + frow * 80 + fhalf * 32;
            cp_async16(d + OFF_BH, g_Vh + o);
            cp_async16(d + OFF_BH + 16, g_Vh + o + 8);
            cp_async16(d + OFF_BL, g_Vl + o);
            cp_async16(d + OFF_BL + 16, g_Vl + o + 8);
        }
    };

    fill(0, 0); CP_COMMIT();
    fill(1, 1); CP_COMMIT();

    for (int chunk = 0; chunk < NCHUNK; ++chunk) {
        const int stage = chunk & 1;
        if (chunk == NCHUNK - 1) { CP_WAIT(0); } else { CP_WAIT(1); }
        __syncthreads();

        const uint32_t sb = smbase + stage * STAGE_BYTES;
#pragma unroll
        for (int s = 0; s < 2; ++s) {
            const int kk0 = s * 16;
            uint32_t Af[4][4], Bhf[2][4], Blf[2][4];
#pragma unroll
            for (int mi = 0; mi < 4; mi++) {
                int row = wm * 64 + mi * 16 + a_row_off;
                ldm_x4(Af[mi], sb + (uint32_t)(row * AP + kk0 + a_col_off) * 2);
            }
#pragma unroll
            for (int g = 0; g < 2; g++) {
                int row = wn * 32 + g * 16 + b_row_off;
                uint32_t off = (uint32_t)(row * AP + kk0 + b_col_off) * 2;
                ldm_x4(Bhf[g], sb + OFF_BH + off);
                ldm_x4(Blf[g], sb + OFF_BL + off);
            }
#pragma unroll
            for (int mi = 0; mi < 4; mi++)
#pragma unroll
                for (int ni = 0; ni < 4; ni++)
                    mma_bf16(C[mi][ni], Af[mi],
                             Bhf[ni >> 1][(ni & 1) * 2],
                             Bhf[ni >> 1][(ni & 1) * 2 + 1]);
#pragma unroll
            for (int mi = 0; mi < 4; mi++)
#pragma unroll
                for (int ni = 0; ni < 4; ni++)
                    mma_bf16(C[mi][ni], Af[mi],
                             Blf[ni >> 1][(ni & 1) * 2],
                             Blf[ni >> 1][(ni & 1) * 2 + 1]);
#pragma unroll
            for (int mi = 0; mi < 4; mi++) {
                int row = wm * 64 + mi * 16 + a_row_off;
                ldm_x4(Af[mi],
                       sb + OFF_AL + (uint32_t)(row * AP + kk0 + a_col_off) * 2);
            }
#pragma unroll
            for (int mi = 0; mi < 4; mi++)
#pragma unroll
                for (int ni = 0; ni < 4; ni++)
                    mma_bf16(C[mi][ni], Af[mi],
                             Bhf[ni >> 1][(ni & 1) * 2],
                             Bhf[ni >> 1][(ni & 1) * 2 + 1]);
        }

        if (chunk + 2 < NCHUNK) {
            __syncthreads();
            fill(chunk + 2, stage);
            CP_COMMIT();
        }
    }

    // epilogue: transpose through smem -> g_M[t][tile][oc]
    __syncthreads();
    float* sC = reinterpret_cast<float*>(dynsm);       // pitch 132
    const int g = lane >> 2, t4 = lane & 3;
#pragma unroll
    for (int mi = 0; mi < 4; mi++) {
        int ocA = wm * 64 + mi * 16 + g;
        int ocB = ocA + 8;
#pragma unroll
        for (int ni = 0; ni < 4; ni++) {
            int nn = wn * 32 + ni * 8 + t4 * 2;
            sC[nn * 132 + ocA] = C[mi][ni][0];
            sC[(nn + 1) * 132 + ocA] = C[mi][ni][1];
            sC[nn * 132 + ocB] = C[mi][ni][2];
            sC[(nn + 1) * 132 + ocB] = C[mi][ni][3];
        }
    }
    __syncthreads();
    float* Mo = g_M + ((size_t)t * NTILE + nt0) * CHN + oc0;
    for (int e = tid; e < 16384; e += 256) {
        int tl = e >> 7, ocl = e & 127;
        Mo[(size_t)tl * CHN + ocl] = sC[tl * 132 + ocl];
    }
}

// ======================= output transform helpers ==========================
__device__ __forceinline__ void at_rows(const float m[6], float o[4]) {
    o[0] = m[0] + m[1] + m[2] + m[3] + m[4];
    o[1] = m[1] - m[2] + 2.f * m[3] - 2.f * m[4];
    o[2] = m[1] + m[2] + 4.f * m[3] + 4.f * m[4];
    o[3] = m[1] - m[2] + 8.f * m[3] - 8.f * m[4] + m[5];
}

// ======================= output transform, conv1 ===========================
__global__ void __launch_bounds__(256)
outx1_kernel() {
    const int ocq = blockIdx.x, ty = blockIdx.y, n = blockIdx.z;
    const int tid = threadIdx.x;
    __nv_bfloat16* hh = g_hh + (size_t)n * PLANE_N;
    __nv_bfloat16* hl = g_hl + (size_t)n * PLANE_N;
#pragma unroll
    for (int it = 0; it < 4; it++) {
        int item = tid + it * 256;
        int oc = ocq * 128 + (item & 127);
        int tx = item >> 7;
        int gtile = n * 64 + ty * 8 + tx;
        float m[36];
#pragma unroll
        for (int t = 0; t < 36; t++)
            m[t] = g_M[((size_t)t * NTILE + gtile) * CHN + oc];
        float tmp[4][6];
#pragma unroll
        for (int j = 0; j < 6; j++) {
            float col[6];
#pragma unroll
            for (int i = 0; i < 6; i++) col[i] = m[i * 6 + j];
            float o[4];
            at_rows(col, o);
#pragma unroll
            for (int i = 0; i < 4; i++) tmp[i][j] = o[i];
        }
        float s = g_bns[oc], b = g_bnb[oc];
#pragma unroll
        for (int i = 0; i < 4; i++) {
            float o[4];
            at_rows(tmp[i], o);
#pragma unroll
            for (int j = 0; j < 4; j++) {
                float v = fmaxf(fmaf(o[j], s, b), 0.f);
                int pos = (4 * ty + i + 1) * 34 + (4 * tx + j + 1);
                split_store(hh, hl, (size_t)pos * CHN + oc, v);
            }
        }
    }
}

// ======================= output transform, conv2 -> x_enc fp32 =============
__global__ void __launch_bounds__(256)
outx2_kernel(float* __restrict__ out) {
    __shared__ float sO[64][132];
    const int ocq = blockIdx.x, ty = blockIdx.y, n = blockIdx.z;
    const int tid = threadIdx.x;
#pragma unroll
    for (int it = 0; it < 2; it++) {
        int item = tid + it * 256;
        int ocl = item & 63;
        int tx = item >> 6;
        int oc = ocq * 64 + ocl;
        int gtile = n * 64 + ty * 8 + tx;
        float m[36];
#pragma unroll
        for (int t = 0; t < 36; t++)
            m[t] = g_M[((size_t)t * NTILE + gtile) * CHN + oc];
        float tmp[4][6];
#pragma unroll
        for (int j = 0; j < 6; j++) {
            float col[6];
#pragma unroll
            for (int i = 0; i < 6; i++) col[i] = m[i * 6 + j];
            float o[4];
            at_rows(col, o);
#pragma unroll
            for (int i = 0; i < 4; i++) tmp[i][j] = o[i];
        }
#pragma unroll
        for (int i = 0; i < 4; i++) {
            float o[4];
            at_rows(tmp[i], o);
#pragma unroll
            for (int j = 0; j < 4; j++)
                sO[ocl][i * 33 + 4 * tx + j] = o[j];
        }
    }
    __syncthreads();
    float* oN = out + ((size_t)n * CHN + ocq * 64) * HWP;
    for (int e = tid; e < 8192; e += 256) {
        int ocl = e >> 7;
        int r2 = e & 127;
        int yy = r2 >> 5, col = r2 & 31;
        oN[(size_t)ocl * HWP + (4 * ty + yy) * 32 + col] = sO[ocl][yy * 33 + col];
    }
}

// ======================= assign + softmax (2-way split, f32x2) =============
__global__ void __launch_bounds__(256)
assign_softmax_kernel(const float* __restrict__ xenc, const float* __restrict__ wa) {
    __shared__ ull s_w2[2][8][32];
    __shared__ float s_part[128][65];
    const int n = blockIdx.x >> 3;
    const int l0 = (blockIdx.x & 7) * 128;
    const int tid = threadIdx.x;
    const int grp = tid >> 7;
    const int lt = tid & 127;
    const int l = l0 + lt;
    const int cbase = grp * 256;
    const float* xN = xenc + (size_t)n * CHN * HWP;

    ull s2[32];
#pragma unroll
    for (int j = 0; j < 32; j++) s2[j] = 0ULL;
    float ss = 0.f;

    for (int c0 = 0; c0 < 256; c0 += 8) {
#pragma unroll
        for (int r = 0; r < 2; r++) {
            int e = lt + r * 128;          // 0..255
            int cc = e >> 5, kp = e & 31;
            int cidx = cbase + c0 + cc;
            s_w2[grp][cc][kp] =
                pack2(wa[(2 * kp) * 512 + cidx], wa[(2 * kp + 1) * 512 + cidx]);
        }
        __syncthreads();
#pragma unroll
        for (int cc = 0; cc < 8; cc++) {
            float xv = xN[(cbase + c0 + cc) * HWP + l];
            ss = fmaf(xv, xv, ss);
            ull xv2 = pack2(xv, xv);
#pragma unroll
            for (int j = 0; j < 32; j++)
                s2[j] = fma2(xv2, s_w2[grp][cc][j], s2[j]);
        }
        __syncthreads();
    }

    float s[64];
#pragma unroll
    for (int j = 0; j < 32; j++) {
        float2 u = unpack2(s2[j]);
        s[2 * j] = u.x;
        s[2 * j + 1] = u.y;
    }

    if (grp == 1) {
#pragma unroll
        for (int k = 0; k < 64; k++) s_part[lt][k] = s[k];
        s_part[lt][64] = ss;
    }
    __syncthreads();
    if (grp == 0) {
#pragma unroll
        for (int k = 0; k < 64; k++) s[k] += s_part[lt][k];
        ss += s_part[lt][64];

        float invn = 1.f / fmaxf(sqrtf(ss), 1e-12f);
        g_invn[n * HWP + l] = invn;

        float mx = -1e30f;
#pragma unroll
        for (int k = 0; k < 64; k++) { s[k] *= invn; mx = fmaxf(mx, s[k]); }
        float sum = 0.f;
#pragma unroll
        for (int k = 0; k < 64; k++) { s[k] = expf(s[k] - mx); sum += s[k]; }
        float rs = 1.f / sum;
#pragma unroll
        for (int k = 0; k < 64; k++)
            g_sa[((size_t)n * 64 + k) * HWP + l] = s[k] * rs;
    }
}

// ======================= ssum =======================
__global__ void ssum_kernel() {
    int row = blockIdx.x;
    int tid = threadIdx.x;
    const float4* p = reinterpret_cast<const float4*>(g_sa + (size_t)row * HWP);
    float4 v = p[tid];
    float t = v.x + v.y + v.z + v.w;
    __shared__ float red[256];
    red[tid] = t;
    __syncthreads();
    for (int s = 128; s > 0; s >>= 1) {
        if (tid < s) red[tid] += red[tid + s];
        __syncthreads();
    }
    if (tid == 0) g_ssum[row] = red[0];
}

// ======================= VLAD: smem-tiled f32x2 GEMM =======================
// Grid (8 cblk, 16 n), block 256, 1 CTA/SM. Each CTA: 64 channels x 64 k.
// Per 256-l chunk: s_sa2[l][kp] (k-pairs), s_x2[l][c] (dup pairs, *invn).
__global__ void __launch_bounds__(256)
vlad_kernel(const float* __restrict__ xenc, const float* __restrict__ cent) {
    extern __shared__ __align__(16) ull vsm[];
    ull* s_sa2 = vsm;            // [256][32]
    ull* s_x2 = vsm + 8192;      // [256][64]

    const int cblk = blockIdx.x, n = blockIdx.y;
    const int c0 = cblk * 64;
    const int tid = threadIdx.x;
    const int kg = tid >> 4;           // 0..15 -> k0 = kg*4
    const int cg = tid & 15;           // c4 = cg*4
    const int k0 = kg * 4, c4 = cg * 4;

    const float* xNc = xenc + ((size_t)n * CHN + c0) * HWP;
    const float* saN = g_sa + (size_t)n * 64 * HWP;
    const float* invN = g_invn + n * HWP;

    ull acc[2][4];
#pragma unroll
    for (int p = 0; p < 2; p++)
#pragma unroll
        for (int j = 0; j < 4; j++) acc[p][j] = 0ULL;

    for (int ch = 0; ch < 4; ch++) {
        const int l0 = ch * 256;
        // fill sa pairs: kp in lanes (conflict-free STS), 8 iters
#pragma unroll
        for (int it = 0; it < 8; it++) {
            int tsk = tid + it * 256;       // 2048 = 64 lq * 32 kp
            int lq = tsk >> 5, kp = tsk & 31;
            const float4 a = *reinterpret_cast<const float4*>(
                saN + (size_t)(2 * kp) * HWP + l0 + 4 * lq);
            const float4 b = *reinterpret_cast<const float4*>(
                saN + (size_t)(2 * kp + 1) * HWP + l0 + 4 * lq);
            s_sa2[(4 * lq + 0) * 32 + kp] = pack2(a.x, b.x);
            s_sa2[(4 * lq + 1) * 32 + kp] = pack2(a.y, b.y);
            s_sa2[(4 * lq + 2) * 32 + kp] = pack2(a.z, b.z);
            s_sa2[(4 * lq + 3) * 32 + kp] = pack2(a.w, b.w);
        }
        // fill x dup pairs (c in lanes -> conflict-free STS), 16 iters
#pragma unroll
        for (int it = 0; it < 16; it++) {
            int tsk = tid + it * 256;       // 4096 = 64 lq * 64 c
            int lq = tsk >> 6, c = tsk & 63;
            const float4 xv = *reinterpret_cast<const float4*>(
                xNc + (size_t)c * HWP + l0 + 4 * lq);
            const float4 iv = *reinterpret_cast<const float4*>(
                invN + l0 + 4 * lq);
            float v0 = xv.x * iv.x, v1 = xv.y * iv.y;
            float v2 = xv.z * iv.z, v3 = xv.w * iv.w;
            s_x2[(4 * lq + 0) * 64 + c] = pack2(v0, v0);
            s_x2[(4 * lq + 1) * 64 + c] = pack2(v1, v1);
            s_x2[(4 * lq + 2) * 64 + c] = pack2(v2, v2);
            s_x2[(4 * lq + 3) * 64 + c] = pack2(v3, v3);
        }
        __syncthreads();

        for (int l = 0; l < 256; l++) {
            ull sa0 = s_sa2[l * 32 + kg * 2];
            ull sa1 = s_sa2[l * 32 + kg * 2 + 1];
            ull x0 = s_x2[l * 64 + c4 + 0];
            ull x1 = s_x2[l * 64 + c4 + 1];
            ull x2 = s_x2[l * 64 + c4 + 2];
            ull x3 = s_x2[l * 64 + c4 + 3];
            acc[0][0] = fma2(sa0, x0, acc[0][0]);
            acc[0][1] = fma2(sa0, x1, acc[0][1]);
            acc[0][2] = fma2(sa0, x2, acc[0][2]);
            acc[0][3] = fma2(sa0, x3, acc[0][3]);
            acc[1][0] = fma2(sa1, x0, acc[1][0]);
            acc[1][1] = fma2(sa1, x1, acc[1][1]);
            acc[1][2] = fma2(sa1, x2, acc[1][2]);
            acc[1][3] = fma2(sa1, x3, acc[1][3]);
        }
        __syncthreads();
    }

    // epilogue: rows k0..k0+3, cols c0+c4..+3
#pragma unroll
    for (int r = 0; r < 4; r++) {
        int k = k0 + r;
        float ssumk = g_ssum[n * 64 + k];
        float4 o;
        float vals[4];
#pragma unroll
        for (int j = 0; j < 4; j++) {
            float2 u = unpack2(acc[r >> 1][j]);
            vals[j] = (r & 1) ? u.y : u.x;
        }
        const float* cr = cent + (size_t)k * CHN + c0 + c4;
        o.x = vals[0] - ssumk * cr[0];
        o.y = vals[1] - ssumk * cr[1];
        o.z = vals[2] - ssumk * cr[2];
        o.w = vals[3] - ssumk * cr[3];
        *reinterpret_cast<float4*>(
            g_vlad + ((size_t)n * 64 + k) * CHN + c0 + c4) = o;
    }
}

// ======================= intra norm =======================
__global__ void intra_kernel(float* __restrict__ out_vlad) {
    int row = blockIdx.x;
    int tid = threadIdx.x;
    const float2* p = reinterpret_cast<const float2*>(g_vlad + (size_t)row * 512);
    float2 v = p[tid];
    float ssq = v.x * v.x + v.y * v.y;
    __shared__ float red[256];
    red[tid] = ssq;
    __syncthreads();
    for (int s = 128; s > 0; s >>= 1) {
        if (tid < s) red[tid] += red[tid + s];
        __syncthreads();
    }
    float ss = red[0];
    float inv = 1.f / fmaxf(sqrtf(ss), 1e-12f);
    float2* o = reinterpret_cast<float2*>(out_vlad + (size_t)row * 512);
    float2 w;
    w.x = v.x * inv;
    w.y = v.y * inv;
    o[tid] = w;
    if (tid == 0) g_rowss[row] = ss * inv * inv;
}

// ======================= global scale =======================
__global__ void gscale_kernel(float* __restrict__ out_vlad) {
    int n = blockIdx.x;
    int tid = threadIdx.x;
    __shared__ float red[64];
    __shared__ float gsc;
    if (tid < 64) red[tid] = g_rowss[n * 64 + tid];
    __syncthreads();
    if (tid == 0) {
        float t = 0.f;
        for (int i = 0; i < 64; i++) t += red[i];
        gsc = 1.f / fmaxf(sqrtf(t), 1e-12f);
    }
    __syncthreads();
    float g = gsc;
    float* o = out_vlad + (size_t)n * (KCL * CHN);
    for (int i = tid; i < KCL * CHN; i += 256) o[i] *= g;
}

// ======================= launcher =======================
extern "C" void kernel_launch(void* const* d_in, const int* in_sizes, int n_in,
                              void* d_out, int out_size) {
    const float* x     = (const float*)d_in[0];
    const float* w1    = (const float*)d_in[1];
    const float* gamma = (const float*)d_in[2];
    const float* beta  = (const float*)d_in[3];
    const float* mean  = (const float*)d_in[4];
    const float* var   = (const float*)d_in[5];
    const float* w2    = (const float*)d_in[6];
    const float* wa    = (const float*)d_in[7];
    const float* cent  = (const float*)d_in[8];

    float* out = (float*)d_out;
    float* out_vlad = out;
    float* out_xenc = out + (size_t)N_IMG * KCL * CHN;

    static int smem_set = 0;
    if (!smem_set) {
        cudaFuncSetAttribute(gemm_wino_kernel,
                             cudaFuncAttributeMaxDynamicSharedMemorySize,
                             GEMM_DSMEM);
        cudaFuncSetAttribute(vlad_kernel,
                             cudaFuncAttributeMaxDynamicSharedMemorySize,
                             VLAD_DSMEM);
        smem_set = 1;
    }

    prep_wino_kernel<<<2048, 256>>>(w1, w2, gamma, beta, mean, var);

    dim3 tgrid(16, 8, N_IMG);
    dim3 ggrid(8, 4, NT);
    dim3 o1grid(4, 8, N_IMG);
    dim3 o2grid(8, 8, N_IMG);

    inx_kernel<<<tgrid, 256>>>(x, 1);
    gemm_wino_kernel<<<ggrid, 256, GEMM_DSMEM>>>(1);
    outx1_kernel<<<o1grid, 256>>>();

    inx_kernel<<<tgrid, 256>>>(nullptr, 2);
    gemm_wino_kernel<<<ggrid, 256, GEMM_DSMEM>>>(2);
    outx2_kernel<<<o2grid, 256>>>(out_xenc);

    assign_softmax_kernel<<<N_IMG * 8, 256>>>(out_xenc, wa);
    ssum_kernel<<<N_IMG * KCL, 256>>>();
    vlad_kernel<<<dim3(8, N_IMG), 256, VLAD_DSMEM>>>(out_xenc, cent);
    intra_kernel<<<N_IMG * KCL, 256>>>(out_vlad);
    gscale_kernel<<<N_IMG, 256>>>(out_vlad);
}